// round 10
// baseline (speedup 1.0000x reference)
#include <cuda_runtime.h>
#include <cuda_fp16.h>
#include <math.h>
#include <stdint.h>

#define K_CODES 1024
#define C_DIM   64
#define N_TOT   32768
#define TILE_N  128
#define CHUNK_K 128
#define N_CHUNKS 8
#define N_BLOCKS (N_TOT / TILE_N)   // 256
#define PREP_BLKS 16

#define Q_ELEMS  (32*64*32*32)      // 2097152
#define LOSS_OFF Q_ELEMS
#define IDX_OFF  (Q_ELEMS + 1)
#define PERP_OFF (Q_ELEMS + 1 + N_TOT)

#define PITCH_B   144               // 9 x 16B: conflict-free ldmatrix rows
#define PLANE_B   18432             // 128 rows x 144 B
#define XPITCH    65                // fp32 x tile pitch (floats)

// smem layout (dynamic)
#define OFF_X32   0                              // 128 x 65 f32 = 33280
#define OFF_AH    33280                          // 18432
#define OFF_B     51712                          // 2 bufs x 18432 = 36864
#define OFF_ENRM  88576                          // 1024 f32 = 4096
#define OFF_T2D   92672                          // 2 x 128 x 2 f32 = 4096
#define OFF_T2I   96768                          // 2 x 128 x 2 i32 = 4096
#define OFF_SIDX  100864                         // 128 ints
#define OFF_SRED  101376                         // 8 f + flag
#define OFF_SCR   OFF_X32                        // finalize scratch (256 f)
#define SMEM_TOTAL 101440                        // x2 = 202.9 KB/SM -> 2 CTAs/SM

// device scratch (no allocations allowed)
__device__ float  g_enrm[K_CODES];
__device__ int    g_counts[K_CODES];
__device__ float  g_loss_partial[N_BLOCKS];
__device__ int    g_ticket;
__device__ float  g_emax2[PREP_BLKS];      // block-max ||e||^2
__device__ float  g_elmax2[PREP_BLKS];     // block-max ||el||^2
__device__ __half g_eh[K_CODES * C_DIM];   // code-major [k][c], fp16 hi

__device__ __forceinline__ uint32_t smem_u32(const void* p) {
    uint32_t a;
    asm("{ .reg .u64 t; cvta.to.shared.u64 t, %1; cvt.u32.u64 %0, t; }" : "=r"(a) : "l"(p));
    return a;
}
__device__ __forceinline__ void cp16(uint32_t dst, const void* src) {
    asm volatile("cp.async.cg.shared.global [%0], [%1], 16;" :: "r"(dst), "l"(src));
}
#define CP_COMMIT() asm volatile("cp.async.commit_group;" ::: "memory")
#define CP_WAIT(n)  asm volatile("cp.async.wait_group %0;" :: "n"(n) : "memory")

#define LDSM_X4(r0,r1,r2,r3,a) \
    asm volatile("ldmatrix.sync.aligned.m8n8.x4.shared.b16 {%0,%1,%2,%3}, [%4];" \
                 : "=r"(r0),"=r"(r1),"=r"(r2),"=r"(r3) : "r"(a))
#define MMA16816(c0,c1,c2,c3,a0,a1,a2,a3,b0,b1) \
    asm volatile("mma.sync.aligned.m16n8k16.row.col.f32.f16.f16.f32 " \
                 "{%0,%1,%2,%3}, {%4,%5,%6,%7}, {%8,%9}, {%0,%1,%2,%3};" \
                 : "+f"(c0),"+f"(c1),"+f"(c2),"+f"(c3) \
                 : "r"(a0),"r"(a1),"r"(a2),"r"(a3),"r"(b0),"r"(b1))

// ---------------------------------------------------------------------------
// Prep: embed -> fp16 hi (code-major), ||e||^2, block maxima of ||e||^2 and
// ||el||^2, zero counts, reset ticket.  16 blocks x 256 threads.
// ---------------------------------------------------------------------------
__global__ __launch_bounds__(256) void vq_prep(const float* __restrict__ embed) {
    __shared__ float tile[64][65];
    __shared__ float nred[4][64], nredl[4][64];
    __shared__ float se2[64], sel2[64];
    const int tid = threadIdx.x;
    const int k0 = blockIdx.x * 64;

    for (int i = tid; i < 4096; i += 256) {
        int c = i >> 6, kk = i & 63;
        tile[c][kk] = embed[c * K_CODES + k0 + kk];
    }
    __syncthreads();

    const int kk = tid & 63, part = tid >> 6;
    float s = 0.f, sl = 0.f;
    uint32_t hw[8];
#pragma unroll
    for (int j = 0; j < 8; ++j) {
        int c0 = part * 16 + j * 2;
        float e0 = tile[c0][kk], e1 = tile[c0 + 1][kk];
        s += e0 * e0 + e1 * e1;
        __half h0 = __float2half_rn(e0), h1 = __float2half_rn(e1);
        float l0 = e0 - __half2float(h0), l1 = e1 - __half2float(h1);
        sl += l0 * l0 + l1 * l1;
        hw[j] = (uint32_t)__half_as_ushort(h0) | ((uint32_t)__half_as_ushort(h1) << 16);
    }
    {
        uint4* dh = (uint4*)&g_eh[(k0 + kk) * C_DIM + part * 16];
        dh[0] = make_uint4(hw[0], hw[1], hw[2], hw[3]);
        dh[1] = make_uint4(hw[4], hw[5], hw[6], hw[7]);
    }
    nred[part][kk] = s;
    nredl[part][kk] = sl;
    __syncthreads();
    if (part == 0) {
        float e2  = nred[0][kk] + nred[1][kk] + nred[2][kk] + nred[3][kk];
        float el2 = nredl[0][kk] + nredl[1][kk] + nredl[2][kk] + nredl[3][kk];
        g_enrm[k0 + kk] = e2;
        g_counts[k0 + kk] = 0;
        se2[kk] = e2;
        sel2[kk] = el2;
    }
    __syncthreads();
    if (tid < 32) {
        float m = fmaxf(se2[tid], se2[tid + 32]);
        float ml = fmaxf(sel2[tid], sel2[tid + 32]);
#pragma unroll
        for (int s2 = 16; s2 > 0; s2 >>= 1) {
            m  = fmaxf(m,  __shfl_xor_sync(0xFFFFFFFFu, m,  s2));
            ml = fmaxf(ml, __shfl_xor_sync(0xFFFFFFFFu, ml, s2));
        }
        if (tid == 0) { g_emax2[blockIdx.x] = m; g_elmax2[blockIdx.x] = ml; }
    }
    if (blockIdx.x == 0 && tid == 0) g_ticket = 0;
}

// ---------------------------------------------------------------------------
// Main: hh-only mma.sync GEMM (1/3 MMA work) + top-2 tracking + exact fp32
// refine of argmin candidates within a provable error bound.
// ---------------------------------------------------------------------------
__device__ __forceinline__ void load_chunk(int ck, int buf, uint32_t sb, int tid) {
    const __half* srch = g_eh + ck * CHUNK_K * C_DIM;
    const uint32_t dbase = sb + OFF_B + buf * PLANE_B;
#pragma unroll
    for (int p = 0; p < 4; ++p) {
        int i = tid + p * 256;                  // granule 0..1023
        int r = i >> 3, g = i & 7;
        cp16(dbase + (uint32_t)(r * PITCH_B + g * 16), srch + i * 8);
    }
    CP_COMMIT();
}

__device__ __forceinline__ void top2_upd(float d, int k, float& d1, int& i1,
                                         float& d2, int& i2) {
    if (d < d1) { d2 = d1; i2 = i1; d1 = d; i1 = k; }
    else if (d < d2) { d2 = d; i2 = k; }
}
__device__ __forceinline__ void top2_merge(float od1, int oi1, float od2, int oi2,
                                           float& d1, int& i1, float& d2, int& i2) {
    // merge two sorted pairs, keep smallest two
    if (od1 < d1) {
        float t = d1; int ti = i1;
        d1 = od1; i1 = oi1;
        d2 = (od2 < t) ? od2 : t;  i2 = (od2 < t) ? oi2 : ti;
    } else {
        if (od1 < d2) { d2 = od1; i2 = oi1; }
    }
}

__global__ __launch_bounds__(256, 2) void vq_main(const float* __restrict__ inputs,
                                                  const float* __restrict__ embed,
                                                  float* __restrict__ out)
{
    extern __shared__ __align__(128) char smem[];
    const uint32_t sb = smem_u32(smem);
    const int tid = threadIdx.x;
    const int wid = tid >> 5, lane = tid & 31;
    const int mw = wid & 3, nh = wid >> 2;
    const int base_n = blockIdx.x * TILE_N;
    const int b = base_n >> 10, hw0 = base_n & 1023;

    float* x32   = (float*)(smem + OFF_X32);
    float* senrm = (float*)(smem + OFF_ENRM);
    float* t2d   = (float*)(smem + OFF_T2D);
    int*   t2i   = (int*)(smem + OFF_T2I);
    int*   sidx  = (int*)(smem + OFF_SIDX);
    float* sred  = (float*)(smem + OFF_SRED);

    // enrm (4KB) + chunk 0 in group 0; chunk 1 in group 1
    if (tid < 256) cp16(sb + OFF_ENRM + tid * 16, g_enrm + tid * 4);
    load_chunk(0, 0, sb, tid);
    load_chunk(1, 1, sb, tid);

    // x tile: fp32 (pitched 65) + fp16-hi plane (pitched 144)
    for (int idx = tid; idx < C_DIM * TILE_N; idx += 256) {
        int c = idx >> 7, nl = idx & 127;
        float x = inputs[b * 65536 + c * 1024 + hw0 + nl];
        x32[nl * XPITCH + c] = x;
        *(__half*)(smem + OFF_AH + nl * PITCH_B + c * 2) = __float2half_rn(x);
    }

    const uint32_t a_addr = sb + OFF_AH + (mw * 32 + (lane & 15)) * PITCH_B
                          + (lane >> 4) * 16;
    const int bm = lane >> 3, bsub = lane & 7;
    const uint32_t b_row_off = (uint32_t)(((bm >> 1) * 8 + bsub) * PITCH_B + (bm & 1) * 16);
    const int ntb = nh * 8;

    // top-2 trackers for 4 (m, row-half) vector slots
    float d1[2][2] = {{3.4e38f, 3.4e38f}, {3.4e38f, 3.4e38f}};
    float d2[2][2] = {{3.4e38f, 3.4e38f}, {3.4e38f, 3.4e38f}};
    int   i1[2][2] = {{0,0},{0,0}}, i2[2][2] = {{0,0},{0,0}};

    for (int ck = 0; ck < N_CHUNKS; ++ck) {
        const int buf = ck & 1;
        if (ck == N_CHUNKS - 1) CP_WAIT(0); else CP_WAIT(1);
        __syncthreads();

        float acc[2][8][4];
#pragma unroll
        for (int m = 0; m < 2; ++m)
#pragma unroll
            for (int t = 0; t < 8; ++t)
#pragma unroll
                for (int q = 0; q < 4; ++q) acc[m][t][q] = 0.f;

        const uint32_t bh_base = sb + OFF_B + buf * PLANE_B;
#pragma unroll
        for (int ks = 0; ks < 4; ++ks) {
            uint32_t ah[2][4];
#pragma unroll
            for (int m = 0; m < 2; ++m)
                LDSM_X4(ah[m][0], ah[m][1], ah[m][2], ah[m][3],
                        a_addr + m * 16 * PITCH_B + ks * 32);
#pragma unroll
            for (int p = 0; p < 4; ++p) {
                const int t0 = p * 2;
                uint32_t b0, b1, b2, b3;
                LDSM_X4(b0, b1, b2, b3,
                        bh_base + (uint32_t)((ntb + t0) * 8 * PITCH_B) + b_row_off + ks * 32);
                MMA16816(acc[0][t0][0],acc[0][t0][1],acc[0][t0][2],acc[0][t0][3],
                         ah[0][0],ah[0][1],ah[0][2],ah[0][3], b0,b1);
                MMA16816(acc[0][t0+1][0],acc[0][t0+1][1],acc[0][t0+1][2],acc[0][t0+1][3],
                         ah[0][0],ah[0][1],ah[0][2],ah[0][3], b2,b3);
                MMA16816(acc[1][t0][0],acc[1][t0][1],acc[1][t0][2],acc[1][t0][3],
                         ah[1][0],ah[1][1],ah[1][2],ah[1][3], b0,b1);
                MMA16816(acc[1][t0+1][0],acc[1][t0+1][1],acc[1][t0+1][2],acc[1][t0+1][3],
                         ah[1][0],ah[1][1],ah[1][2],ah[1][3], b2,b3);
            }
        }

        // free the buffer, start next load, then do epilogue (overlaps copy)
        __syncthreads();
        if (ck + 2 < N_CHUNKS) load_chunk(ck + 2, buf, sb, tid);

        const int k0c = ck * CHUNK_K;
#pragma unroll
        for (int t = 0; t < 8; ++t) {
            int kl = (ntb + t) * 8 + (lane & 3) * 2;
            float2 en = *(const float2*)(senrm + kl + k0c);
            int kc = k0c + kl;
#pragma unroll
            for (int m = 0; m < 2; ++m) {
                top2_upd(en.x - 2.f * acc[m][t][0], kc,     d1[m][0], i1[m][0], d2[m][0], i2[m][0]);
                top2_upd(en.y - 2.f * acc[m][t][1], kc + 1, d1[m][0], i1[m][0], d2[m][0], i2[m][0]);
                top2_upd(en.x - 2.f * acc[m][t][2], kc,     d1[m][1], i1[m][1], d2[m][1], i2[m][1]);
                top2_upd(en.y - 2.f * acc[m][t][3], kc + 1, d1[m][1], i1[m][1], d2[m][1], i2[m][1]);
            }
        }
    }

    // combine top-2 across the 4 lanes sharing each row
#pragma unroll
    for (int m = 0; m < 2; ++m)
#pragma unroll
        for (int h = 0; h < 2; ++h) {
#pragma unroll
            for (int s = 1; s < 4; s <<= 1) {
                float od1 = __shfl_xor_sync(0xFFFFFFFFu, d1[m][h], s);
                int   oi1 = __shfl_xor_sync(0xFFFFFFFFu, i1[m][h], s);
                float od2 = __shfl_xor_sync(0xFFFFFFFFu, d2[m][h], s);
                int   oi2 = __shfl_xor_sync(0xFFFFFFFFu, i2[m][h], s);
                top2_merge(od1, oi1, od2, oi2, d1[m][h], i1[m][h], d2[m][h], i2[m][h]);
            }
        }
    if ((lane & 3) == 0) {
#pragma unroll
        for (int m = 0; m < 2; ++m)
#pragma unroll
            for (int h = 0; h < 2; ++h) {
                int r = mw * 32 + m * 16 + (lane >> 2) + h * 8;
                t2d[nh * 256 + r * 2]     = d1[m][h];
                t2d[nh * 256 + r * 2 + 1] = d2[m][h];
                t2i[nh * 256 + r * 2]     = i1[m][h];
                t2i[nh * 256 + r * 2 + 1] = i2[m][h];
            }
    }
    __syncthreads();

    // per-vector exact refine (thread v handles vector v)
    if (tid < TILE_N) {
        const int v = tid;
        // per-vector fp16-split norms for the error bound
        float xh2 = 0.f, xl2 = 0.f;
#pragma unroll 8
        for (int c = 0; c < C_DIM; ++c) {
            float x = x32[v * XPITCH + c];
            float h = __half2float(__float2half_rn(x));
            float l = x - h;
            xh2 += h * h; xl2 += l * l;
        }
        float em2 = 0.f, elm2 = 0.f;
#pragma unroll
        for (int j = 0; j < PREP_BLKS; ++j) {
            em2 = fmaxf(em2, g_emax2[j]);
            elm2 = fmaxf(elm2, g_elmax2[j]);
        }
        float eps = 4.2f * (sqrtf(xl2) * sqrtf(em2) + sqrtf(xh2) * sqrtf(elm2)) + 2e-3f;

        float cd[4]; int ci[4];
        cd[0] = t2d[v * 2];       ci[0] = t2i[v * 2];
        cd[1] = t2d[v * 2 + 1];   ci[1] = t2i[v * 2 + 1];
        cd[2] = t2d[256 + v * 2];     ci[2] = t2i[256 + v * 2];
        cd[3] = t2d[256 + v * 2 + 1]; ci[3] = t2i[256 + v * 2 + 1];
        float gmin = fminf(fminf(cd[0], cd[1]), fminf(cd[2], cd[3]));
        float thr = gmin + eps;

        float bestd = 3.4e38f; int besti = K_CODES;
#pragma unroll
        for (int j = 0; j < 4; ++j) {
            if (cd[j] <= thr) {
                int k = ci[j];
                float dot = 0.f;
#pragma unroll 8
                for (int c = 0; c < C_DIM; ++c)
                    dot += x32[v * XPITCH + c] * __ldg(&embed[c * K_CODES + k]);
                float d = senrm[k] - 2.f * dot;
                if (d < bestd || (d == bestd && k < besti)) { bestd = d; besti = k; }
            }
        }
        sidx[v] = besti;
        out[IDX_OFF + base_n + v] = (float)besti;
        atomicAdd(&g_counts[besti], 1);
    }
    __syncthreads();

    // gather quantized, write coalesced, loss partial (deterministic order)
    float lsum = 0.f;
    for (int idx = tid; idx < C_DIM * TILE_N; idx += 256) {
        int c = idx >> 7, nl = idx & 127;
        int kq = sidx[nl];
        float q = __ldg(&embed[c * K_CODES + kq]);
        float x = x32[nl * XPITCH + c];
        out[b * 65536 + c * 1024 + hw0 + nl] = q;
        float dv = q - x;
        lsum += dv * dv;
    }
#pragma unroll
    for (int s = 16; s > 0; s >>= 1) lsum += __shfl_xor_sync(0xFFFFFFFFu, lsum, s);
    if (lane == 0) sred[wid] = lsum;
    __syncthreads();
    if (tid == 0) {
        float s = 0.f;
#pragma unroll
        for (int w = 0; w < 8; ++w) s += sred[w];
        g_loss_partial[blockIdx.x] = s;
    }

    // ---- last-CTA finalize (loss + perplexity), deterministic trees ----
    __threadfence();
    __syncthreads();
    int* flag = (int*)(smem + OFF_SRED + 32);
    if (tid == 0) {
        int old = atomicAdd(&g_ticket, 1);
        *flag = (old == N_BLOCKS - 1);
    }
    __syncthreads();
    if (*flag) {
        __threadfence();
        float* scr = (float*)(smem + OFF_SCR);
        float ps = 0.f;
#pragma unroll
        for (int j = 0; j < 4; ++j) {
            int k = tid + j * 256;
            float p = (float)g_counts[k] * (1.f / 32768.f);
            ps += p * logf(p + 1e-10f);
        }
        scr[tid] = ps;
        __syncthreads();
        for (int s = 128; s > 0; s >>= 1) {
            if (tid < s) scr[tid] += scr[tid + s];
            __syncthreads();
        }
        if (tid == 0) out[PERP_OFF] = expf(-scr[0]);
        __syncthreads();
        scr[tid] = g_loss_partial[tid];
        __syncthreads();
        for (int s = 128; s > 0; s >>= 1) {
            if (tid < s) scr[tid] += scr[tid + s];
            __syncthreads();
        }
        if (tid == 0) out[LOSS_OFF] = 0.25f * scr[0] / (float)Q_ELEMS;
    }
}

// ---------------------------------------------------------------------------
extern "C" void kernel_launch(void* const* d_in, const int* in_sizes, int n_in,
                              void* d_out, int out_size) {
    const float* inputs = (const float*)d_in[0];
    const float* embed  = (const float*)d_in[1];
    if (n_in >= 2 && in_sizes[0] == K_CODES * C_DIM && in_sizes[1] == Q_ELEMS) {
        const float* t = inputs; inputs = embed; embed = t;
    }
    float* out = (float*)d_out;

    static int smem_set = 0;
    if (!smem_set) {
        cudaFuncSetAttribute(vq_main, cudaFuncAttributeMaxDynamicSharedMemorySize,
                             SMEM_TOTAL);
        smem_set = 1;
    }

    vq_prep<<<PREP_BLKS, 256>>>(embed);
    vq_main<<<N_BLOCKS, 256, SMEM_TOTAL>>>(inputs, embed, out);
}

// round 11
// speedup vs baseline: 1.0537x; 1.0537x over previous
#include <cuda_runtime.h>
#include <cuda_fp16.h>
#include <math.h>
#include <stdint.h>

#define K_CODES 1024
#define C_DIM   64
#define N_TOT   32768
#define TILE_N  128
#define CHUNK_K 64
#define N_CHUNKS 16
#define N_BLOCKS (N_TOT / TILE_N)   // 256
#define PREP_BLKS 16

#define Q_ELEMS  (32*64*32*32)      // 2097152
#define LOSS_OFF Q_ELEMS
#define IDX_OFF  (Q_ELEMS + 1)
#define PERP_OFF (Q_ELEMS + 1 + N_TOT)

#define PITCH_B   144               // 9 x 16B: conflict-free ldmatrix rows
#define PLANE_BB  9216              // 64 rows x 144 B (one B chunk)
#define XPITCH    65

// smem layout (dynamic)
#define OFF_X32   0                 // 128 x 65 f32 = 33280
#define OFF_AH    33280             // 128 x 144 = 18432
#define OFF_B     51712             // 3 bufs x 9216 = 27648
#define OFF_ENRM  79360             // 1024 f32 = 4096
#define OFF_T2D   83456             // 2 x 128 x 2 f32 = 4096
#define OFF_T2I   87552             // 4096
#define OFF_SIDX  91648             // 128 ints
#define OFF_SRED  92160             // 8 f + flag
#define OFF_SCR   OFF_X32           // finalize scratch
#define SMEM_TOTAL 92224            // x2 = 184.4 KB/SM -> 2 CTAs/SM

// device scratch (no allocations allowed)
__device__ float  g_enrm[K_CODES];
__device__ int    g_counts[K_CODES];
__device__ float  g_loss_partial[N_BLOCKS];
__device__ int    g_ticket;
__device__ float  g_emax2[PREP_BLKS];
__device__ float  g_elmax2[PREP_BLKS];
__device__ __half g_eh[K_CODES * C_DIM];   // code-major [k][c], fp16 hi

__device__ __forceinline__ uint32_t smem_u32(const void* p) {
    uint32_t a;
    asm("{ .reg .u64 t; cvta.to.shared.u64 t, %1; cvt.u32.u64 %0, t; }" : "=r"(a) : "l"(p));
    return a;
}
__device__ __forceinline__ void cp16(uint32_t dst, const void* src) {
    asm volatile("cp.async.cg.shared.global [%0], [%1], 16;" :: "r"(dst), "l"(src));
}
#define CP_COMMIT() asm volatile("cp.async.commit_group;" ::: "memory")
#define CP_WAIT(n)  asm volatile("cp.async.wait_group %0;" :: "n"(n) : "memory")

#define LDSM_X4(r0,r1,r2,r3,a) \
    asm volatile("ldmatrix.sync.aligned.m8n8.x4.shared.b16 {%0,%1,%2,%3}, [%4];" \
                 : "=r"(r0),"=r"(r1),"=r"(r2),"=r"(r3) : "r"(a))
#define MMA16816(c0,c1,c2,c3,a0,a1,a2,a3,b0,b1) \
    asm volatile("mma.sync.aligned.m16n8k16.row.col.f32.f16.f16.f32 " \
                 "{%0,%1,%2,%3}, {%4,%5,%6,%7}, {%8,%9}, {%0,%1,%2,%3};" \
                 : "+f"(c0),"+f"(c1),"+f"(c2),"+f"(c3) \
                 : "r"(a0),"r"(a1),"r"(a2),"r"(a3),"r"(b0),"r"(b1))

// ---------------------------------------------------------------------------
// Prep (unchanged from R10)
// ---------------------------------------------------------------------------
__global__ __launch_bounds__(256) void vq_prep(const float* __restrict__ embed) {
    __shared__ float tile[64][65];
    __shared__ float nred[4][64], nredl[4][64];
    __shared__ float se2[64], sel2[64];
    const int tid = threadIdx.x;
    const int k0 = blockIdx.x * 64;

    for (int i = tid; i < 4096; i += 256) {
        int c = i >> 6, kk = i & 63;
        tile[c][kk] = embed[c * K_CODES + k0 + kk];
    }
    __syncthreads();

    const int kk = tid & 63, part = tid >> 6;
    float s = 0.f, sl = 0.f;
    uint32_t hw[8];
#pragma unroll
    for (int j = 0; j < 8; ++j) {
        int c0 = part * 16 + j * 2;
        float e0 = tile[c0][kk], e1 = tile[c0 + 1][kk];
        s += e0 * e0 + e1 * e1;
        __half h0 = __float2half_rn(e0), h1 = __float2half_rn(e1);
        float l0 = e0 - __half2float(h0), l1 = e1 - __half2float(h1);
        sl += l0 * l0 + l1 * l1;
        hw[j] = (uint32_t)__half_as_ushort(h0) | ((uint32_t)__half_as_ushort(h1) << 16);
    }
    {
        uint4* dh = (uint4*)&g_eh[(k0 + kk) * C_DIM + part * 16];
        dh[0] = make_uint4(hw[0], hw[1], hw[2], hw[3]);
        dh[1] = make_uint4(hw[4], hw[5], hw[6], hw[7]);
    }
    nred[part][kk] = s;
    nredl[part][kk] = sl;
    __syncthreads();
    if (part == 0) {
        float e2  = nred[0][kk] + nred[1][kk] + nred[2][kk] + nred[3][kk];
        float el2 = nredl[0][kk] + nredl[1][kk] + nredl[2][kk] + nredl[3][kk];
        g_enrm[k0 + kk] = e2;
        g_counts[k0 + kk] = 0;
        se2[kk] = e2;
        sel2[kk] = el2;
    }
    __syncthreads();
    if (tid < 32) {
        float m = fmaxf(se2[tid], se2[tid + 32]);
        float ml = fmaxf(sel2[tid], sel2[tid + 32]);
#pragma unroll
        for (int s2 = 16; s2 > 0; s2 >>= 1) {
            m  = fmaxf(m,  __shfl_xor_sync(0xFFFFFFFFu, m,  s2));
            ml = fmaxf(ml, __shfl_xor_sync(0xFFFFFFFFu, ml, s2));
        }
        if (tid == 0) { g_emax2[blockIdx.x] = m; g_elmax2[blockIdx.x] = ml; }
    }
    if (blockIdx.x == 0 && tid == 0) g_ticket = 0;
}

// ---------------------------------------------------------------------------
// Main: hh-only GEMM, 3-deep B buffers (1 barrier/chunk), epilogue of chunk
// k-1 pipelined into MMA loop of chunk k; exact fp32 refine.
// ---------------------------------------------------------------------------
__device__ __forceinline__ void load_chunk(int ck, int buf, uint32_t sb, int tid) {
    const __half* srch = g_eh + ck * CHUNK_K * C_DIM;
    const uint32_t dbase = sb + OFF_B + buf * PLANE_BB;
#pragma unroll
    for (int p = 0; p < 2; ++p) {
        int i = tid + p * 256;                  // granule 0..511
        int r = i >> 3, g = i & 7;
        cp16(dbase + (uint32_t)(r * PITCH_B + g * 16), srch + i * 8);
    }
    CP_COMMIT();
}

__device__ __forceinline__ void top2_upd(float d, int k, float& d1, int& i1,
                                         float& d2, int& i2) {
    if (d < d1) { d2 = d1; i2 = i1; d1 = d; i1 = k; }
    else if (d < d2) { d2 = d; i2 = k; }
}
__device__ __forceinline__ void top2_merge(float od1, int oi1, float od2, int oi2,
                                           float& d1, int& i1, float& d2, int& i2) {
    if (od1 < d1) {
        float t = d1; int ti = i1;
        d1 = od1; i1 = oi1;
        d2 = (od2 < t) ? od2 : t;  i2 = (od2 < t) ? oi2 : ti;
    } else {
        if (od1 < d2) { d2 = od1; i2 = oi1; }
    }
}

__device__ __forceinline__ void chunk_body(
    int ck, uint32_t sb, int tid, int lane, int nh,
    uint32_t a_addr, uint32_t b_row_off,
    float (&cur)[2][4][4], float (&prev)[2][4][4],
    float (&d1)[2][2], float (&d2)[2][2], int (&i1)[2][2], int (&i2)[2][2],
    const float* senrm)
{
    if (ck == N_CHUNKS - 1) { CP_WAIT(0); } else { CP_WAIT(1); }
    __syncthreads();    // chunk ck visible; all warps done with chunk ck-1
    if (ck + 2 < N_CHUNKS) load_chunk(ck + 2, (ck + 2) % 3, sb, tid);

#pragma unroll
    for (int m = 0; m < 2; ++m)
#pragma unroll
        for (int t = 0; t < 4; ++t)
#pragma unroll
            for (int q = 0; q < 4; ++q) cur[m][t][q] = 0.f;

    const uint32_t bbase = sb + OFF_B + (uint32_t)((ck % 3) * PLANE_BB);
    const int pk0 = (ck - 1) * CHUNK_K;
#pragma unroll
    for (int ks = 0; ks < 4; ++ks) {
        uint32_t ah[2][4];
#pragma unroll
        for (int m = 0; m < 2; ++m)
            LDSM_X4(ah[m][0], ah[m][1], ah[m][2], ah[m][3],
                    a_addr + m * 16 * PITCH_B + ks * 32);
#pragma unroll
        for (int p = 0; p < 2; ++p) {
            const int t0 = p * 2;
            uint32_t b0, b1, b2, b3;
            LDSM_X4(b0, b1, b2, b3,
                    bbase + (uint32_t)((nh * 4 + t0) * 8 * PITCH_B) + b_row_off + ks * 32);
            MMA16816(cur[0][t0][0],cur[0][t0][1],cur[0][t0][2],cur[0][t0][3],
                     ah[0][0],ah[0][1],ah[0][2],ah[0][3], b0,b1);
            MMA16816(cur[0][t0+1][0],cur[0][t0+1][1],cur[0][t0+1][2],cur[0][t0+1][3],
                     ah[0][0],ah[0][1],ah[0][2],ah[0][3], b2,b3);
            MMA16816(cur[1][t0][0],cur[1][t0][1],cur[1][t0][2],cur[1][t0][3],
                     ah[1][0],ah[1][1],ah[1][2],ah[1][3], b0,b1);
            MMA16816(cur[1][t0+1][0],cur[1][t0+1][1],cur[1][t0+1][2],cur[1][t0+1][3],
                     ah[1][0],ah[1][1],ah[1][2],ah[1][3], b2,b3);
        }
        // pipelined epilogue: t=ks of PREVIOUS chunk (hides in MMA shadow)
        if (ck > 0) {
            int kl = (nh * 4 + ks) * 8 + (lane & 3) * 2;
            float2 en = *(const float2*)(senrm + pk0 + kl);
            int kc = pk0 + kl;
#pragma unroll
            for (int m = 0; m < 2; ++m) {
                top2_upd(en.x - 2.f * prev[m][ks][0], kc,     d1[m][0], i1[m][0], d2[m][0], i2[m][0]);
                top2_upd(en.y - 2.f * prev[m][ks][1], kc + 1, d1[m][0], i1[m][0], d2[m][0], i2[m][0]);
                top2_upd(en.x - 2.f * prev[m][ks][2], kc,     d1[m][1], i1[m][1], d2[m][1], i2[m][1]);
                top2_upd(en.y - 2.f * prev[m][ks][3], kc + 1, d1[m][1], i1[m][1], d2[m][1], i2[m][1]);
            }
        }
    }
}

__global__ __launch_bounds__(256, 2) void vq_main(const float* __restrict__ inputs,
                                                  const float* __restrict__ embed,
                                                  float* __restrict__ out)
{
    extern __shared__ __align__(128) char smem[];
    const uint32_t sb = smem_u32(smem);
    const int tid = threadIdx.x;
    const int wid = tid >> 5, lane = tid & 31;
    const int mw = wid & 3, nh = wid >> 2;
    const int base_n = blockIdx.x * TILE_N;
    const int b = base_n >> 10, hw0 = base_n & 1023;

    float* x32   = (float*)(smem + OFF_X32);
    float* senrm = (float*)(smem + OFF_ENRM);
    float* t2d   = (float*)(smem + OFF_T2D);
    int*   t2i   = (int*)(smem + OFF_T2I);
    int*   sidx  = (int*)(smem + OFF_SIDX);
    float* sred  = (float*)(smem + OFF_SRED);

    if (tid < 256) cp16(sb + OFF_ENRM + tid * 16, g_enrm + tid * 4);
    load_chunk(0, 0, sb, tid);      // group 0 (incl. enrm)
    load_chunk(1, 1, sb, tid);      // group 1

    for (int idx = tid; idx < C_DIM * TILE_N; idx += 256) {
        int c = idx >> 7, nl = idx & 127;
        float x = inputs[b * 65536 + c * 1024 + hw0 + nl];
        x32[nl * XPITCH + c] = x;
        *(__half*)(smem + OFF_AH + nl * PITCH_B + c * 2) = __float2half_rn(x);
    }

    const uint32_t a_addr = sb + OFF_AH + (mw * 32 + (lane & 15)) * PITCH_B
                          + (lane >> 4) * 16;
    const int bm = lane >> 3, bsub = lane & 7;
    const uint32_t b_row_off = (uint32_t)(((bm >> 1) * 8 + bsub) * PITCH_B + (bm & 1) * 16);

    float accA[2][4][4], accB[2][4][4];
    float d1[2][2] = {{3.4e38f, 3.4e38f}, {3.4e38f, 3.4e38f}};
    float d2[2][2] = {{3.4e38f, 3.4e38f}, {3.4e38f, 3.4e38f}};
    int   i1[2][2] = {{0,0},{0,0}}, i2[2][2] = {{0,0},{0,0}};

    for (int ck2 = 0; ck2 < N_CHUNKS; ck2 += 2) {
        chunk_body(ck2,     sb, tid, lane, nh, a_addr, b_row_off,
                   accA, accB, d1, d2, i1, i2, senrm);
        chunk_body(ck2 + 1, sb, tid, lane, nh, a_addr, b_row_off,
                   accB, accA, d1, d2, i1, i2, senrm);
    }
    // final epilogue: chunk 15 results live in accB
    {
        const int pk0 = (N_CHUNKS - 1) * CHUNK_K;
#pragma unroll
        for (int t = 0; t < 4; ++t) {
            int kl = (nh * 4 + t) * 8 + (lane & 3) * 2;
            float2 en = *(const float2*)(senrm + pk0 + kl);
            int kc = pk0 + kl;
#pragma unroll
            for (int m = 0; m < 2; ++m) {
                top2_upd(en.x - 2.f * accB[m][t][0], kc,     d1[m][0], i1[m][0], d2[m][0], i2[m][0]);
                top2_upd(en.y - 2.f * accB[m][t][1], kc + 1, d1[m][0], i1[m][0], d2[m][0], i2[m][0]);
                top2_upd(en.x - 2.f * accB[m][t][2], kc,     d1[m][1], i1[m][1], d2[m][1], i2[m][1]);
                top2_upd(en.y - 2.f * accB[m][t][3], kc + 1, d1[m][1], i1[m][1], d2[m][1], i2[m][1]);
            }
        }
    }

    // combine top-2 across the 4 lanes sharing each row
#pragma unroll
    for (int m = 0; m < 2; ++m)
#pragma unroll
        for (int h = 0; h < 2; ++h) {
#pragma unroll
            for (int s = 1; s < 4; s <<= 1) {
                float od1 = __shfl_xor_sync(0xFFFFFFFFu, d1[m][h], s);
                int   oi1 = __shfl_xor_sync(0xFFFFFFFFu, i1[m][h], s);
                float od2 = __shfl_xor_sync(0xFFFFFFFFu, d2[m][h], s);
                int   oi2 = __shfl_xor_sync(0xFFFFFFFFu, i2[m][h], s);
                top2_merge(od1, oi1, od2, oi2, d1[m][h], i1[m][h], d2[m][h], i2[m][h]);
            }
        }
    if ((lane & 3) == 0) {
#pragma unroll
        for (int m = 0; m < 2; ++m)
#pragma unroll
            for (int h = 0; h < 2; ++h) {
                int r = mw * 32 + m * 16 + (lane >> 2) + h * 8;
                t2d[nh * 256 + r * 2]     = d1[m][h];
                t2d[nh * 256 + r * 2 + 1] = d2[m][h];
                t2i[nh * 256 + r * 2]     = i1[m][h];
                t2i[nh * 256 + r * 2 + 1] = i2[m][h];
            }
    }
    __syncthreads();

    // per-vector exact refine (thread v handles vector v)
    if (tid < TILE_N) {
        const int v = tid;
        float xh2 = 0.f, xl2 = 0.f;
#pragma unroll 8
        for (int c = 0; c < C_DIM; ++c) {
            float x = x32[v * XPITCH + c];
            float h = __half2float(__float2half_rn(x));
            float l = x - h;
            xh2 += h * h; xl2 += l * l;
        }
        float em2 = 0.f, elm2 = 0.f;
#pragma unroll
        for (int j = 0; j < PREP_BLKS; ++j) {
            em2 = fmaxf(em2, g_emax2[j]);
            elm2 = fmaxf(elm2, g_elmax2[j]);
        }
        float eps = 4.2f * (sqrtf(xl2) * sqrtf(em2) + sqrtf(xh2) * sqrtf(elm2)) + 2e-3f;

        float cd[4]; int ci[4];
        cd[0] = t2d[v * 2];       ci[0] = t2i[v * 2];
        cd[1] = t2d[v * 2 + 1];   ci[1] = t2i[v * 2 + 1];
        cd[2] = t2d[256 + v * 2];     ci[2] = t2i[256 + v * 2];
        cd[3] = t2d[256 + v * 2 + 1]; ci[3] = t2i[256 + v * 2 + 1];
        float gmin = fminf(fminf(cd[0], cd[1]), fminf(cd[2], cd[3]));
        float thr = gmin + eps;

        float bestd = 3.4e38f; int besti = K_CODES;
#pragma unroll
        for (int j = 0; j < 4; ++j) {
            if (cd[j] <= thr) {
                int k = ci[j];
                float dot = 0.f;
#pragma unroll 8
                for (int c = 0; c < C_DIM; ++c)
                    dot += x32[v * XPITCH + c] * __ldg(&embed[c * K_CODES + k]);
                float d = senrm[k] - 2.f * dot;
                if (d < bestd || (d == bestd && k < besti)) { bestd = d; besti = k; }
            }
        }
        sidx[v] = besti;
        out[IDX_OFF + base_n + v] = (float)besti;
        atomicAdd(&g_counts[besti], 1);
    }
    __syncthreads();

    // gather quantized, write coalesced, loss partial (deterministic order)
    float lsum = 0.f;
    for (int idx = tid; idx < C_DIM * TILE_N; idx += 256) {
        int c = idx >> 7, nl = idx & 127;
        int kq = sidx[nl];
        float q = __ldg(&embed[c * K_CODES + kq]);
        float x = x32[nl * XPITCH + c];
        out[b * 65536 + c * 1024 + hw0 + nl] = q;
        float dv = q - x;
        lsum += dv * dv;
    }
#pragma unroll
    for (int s = 16; s > 0; s >>= 1) lsum += __shfl_xor_sync(0xFFFFFFFFu, lsum, s);
    if (lane == 0) sred[wid] = lsum;
    __syncthreads();
    if (tid == 0) {
        float s = 0.f;
#pragma unroll
        for (int w = 0; w < 8; ++w) s += sred[w];
        g_loss_partial[blockIdx.x] = s;
    }

    // ---- last-CTA finalize (loss + perplexity), deterministic trees ----
    __threadfence();
    __syncthreads();
    int* flag = (int*)(smem + OFF_SRED + 32);
    if (tid == 0) {
        int old = atomicAdd(&g_ticket, 1);
        *flag = (old == N_BLOCKS - 1);
    }
    __syncthreads();
    if (*flag) {
        __threadfence();
        float* scr = (float*)(smem + OFF_SCR);
        float ps = 0.f;
#pragma unroll
        for (int j = 0; j < 4; ++j) {
            int k = tid + j * 256;
            float p = (float)g_counts[k] * (1.f / 32768.f);
            ps += p * logf(p + 1e-10f);
        }
        scr[tid] = ps;
        __syncthreads();
        for (int s = 128; s > 0; s >>= 1) {
            if (tid < s) scr[tid] += scr[tid + s];
            __syncthreads();
        }
        if (tid == 0) out[PERP_OFF] = expf(-scr[0]);
        __syncthreads();
        scr[tid] = g_loss_partial[tid];
        __syncthreads();
        for (int s = 128; s > 0; s >>= 1) {
            if (tid < s) scr[tid] += scr[tid + s];
            __syncthreads();
        }
        if (tid == 0) out[LOSS_OFF] = 0.25f * scr[0] / (float)Q_ELEMS;
    }
}

// ---------------------------------------------------------------------------
extern "C" void kernel_launch(void* const* d_in, const int* in_sizes, int n_in,
                              void* d_out, int out_size) {
    const float* inputs = (const float*)d_in[0];
    const float* embed  = (const float*)d_in[1];
    if (n_in >= 2 && in_sizes[0] == K_CODES * C_DIM && in_sizes[1] == Q_ELEMS) {
        const float* t = inputs; inputs = embed; embed = t;
    }
    float* out = (float*)d_out;

    static int smem_set = 0;
    if (!smem_set) {
        cudaFuncSetAttribute(vq_main, cudaFuncAttributeMaxDynamicSharedMemorySize,
                             SMEM_TOTAL);
        smem_set = 1;
    }

    vq_prep<<<PREP_BLKS, 256>>>(embed);
    vq_main<<<N_BLOCKS, 256, SMEM_TOTAL>>>(inputs, embed, out);
}

// round 15
// speedup vs baseline: 1.3645x; 1.2950x over previous
#include <cuda_runtime.h>
#include <cuda_fp16.h>
#include <math.h>
#include <stdint.h>

#define K_CODES 1024
#define C_DIM   64
#define N_TOT   32768
#define TILE_N  128
#define CHUNK_K 128
#define N_CHUNKS 8
#define N_BLOCKS (N_TOT / TILE_N)   // 256
#define PREP_BLKS 16

#define Q_ELEMS  (32*64*32*32)      // 2097152
#define LOSS_OFF Q_ELEMS
#define IDX_OFF  (Q_ELEMS + 1)
#define PERP_OFF (Q_ELEMS + 1 + N_TOT)

#define PITCH_B   144               // 9 x 16B: conflict-free ldmatrix rows
#define PLANE_B   18432             // 128 rows x 144 B
#define XPITCH    65

// smem layout (dynamic)
#define OFF_X32   0                 // 128 x 65 f32 = 33280
#define OFF_AH    33280             // 18432
#define OFF_B     51712             // 2 bufs x 18432 = 36864
#define OFF_ENRM  88576             // 1024 f32 (enrm + 256)
#define OFF_CAND  92672             // 128 x 16 u32 = 8192
#define OFF_SIDX  100864            // 128 ints
#define OFF_SRED  101376            // 8 f + flag
#define OFF_SCR   OFF_X32           // finalize scratch
#define SMEM_TOTAL 101440           // x2 = 202.9 KB/SM -> 2 CTAs/SM

// device scratch (no allocations allowed)
__device__ float  g_enrm[K_CODES];           // true ||e||^2
__device__ float  g_ecm[K_CODES * C_DIM];    // fp32 embed, code-major (refine)
__device__ int    g_counts[K_CODES];
__device__ float  g_loss_partial[N_BLOCKS];
__device__ int    g_ticket;
__device__ float  g_emax2[PREP_BLKS];
__device__ float  g_elmax2[PREP_BLKS];
__device__ __half g_eh[K_CODES * C_DIM];     // fp16 hi, code-major

__device__ __forceinline__ uint32_t smem_u32(const void* p) {
    uint32_t a;
    asm("{ .reg .u64 t; cvta.to.shared.u64 t, %1; cvt.u32.u64 %0, t; }" : "=r"(a) : "l"(p));
    return a;
}
__device__ __forceinline__ void cp16(uint32_t dst, const void* src) {
    asm volatile("cp.async.cg.shared.global [%0], [%1], 16;" :: "r"(dst), "l"(src));
}
#define CP_COMMIT() asm volatile("cp.async.commit_group;" ::: "memory")
#define CP_WAIT(n)  asm volatile("cp.async.wait_group %0;" :: "n"(n) : "memory")

#define LDSM_X4(r0,r1,r2,r3,a) \
    asm volatile("ldmatrix.sync.aligned.m8n8.x4.shared.b16 {%0,%1,%2,%3}, [%4];" \
                 : "=r"(r0),"=r"(r1),"=r"(r2),"=r"(r3) : "r"(a))
#define MMA16816(c0,c1,c2,c3,a0,a1,a2,a3,b0,b1) \
    asm volatile("mma.sync.aligned.m16n8k16.row.col.f32.f16.f16.f32 " \
                 "{%0,%1,%2,%3}, {%4,%5,%6,%7}, {%8,%9}, {%0,%1,%2,%3};" \
                 : "+f"(c0),"+f"(c1),"+f"(c2),"+f"(c3) \
                 : "r"(a0),"r"(a1),"r"(a2),"r"(a3),"r"(b0),"r"(b1))

// branch-free top-2 update on packed keys (3 IMNMX-class ops)
__device__ __forceinline__ void pk2_upd(uint32_t k, uint32_t& p1, uint32_t& p2) {
    uint32_t lo = min(p1, k);
    uint32_t hi = max(p1, k);
    p2 = min(p2, hi);
    p1 = lo;
}

// ---------------------------------------------------------------------------
// Prep: embed -> fp16 hi (code-major) + fp32 code-major copy, ||e||^2,
// split-norm maxima, zero counts, reset ticket.
// ---------------------------------------------------------------------------
__global__ __launch_bounds__(256) void vq_prep(const float* __restrict__ embed) {
    __shared__ float tile[64][65];
    __shared__ float nred[4][64], nredl[4][64];
    __shared__ float se2[64], sel2[64];
    const int tid = threadIdx.x;
    const int k0 = blockIdx.x * 64;

    for (int i = tid; i < 4096; i += 256) {
        int c = i >> 6, kk = i & 63;
        tile[c][kk] = embed[c * K_CODES + k0 + kk];
    }
    __syncthreads();

    const int kk = tid & 63, part = tid >> 6;
    float s = 0.f, sl = 0.f;
    uint32_t hw[8];
    float er[16];
#pragma unroll
    for (int j = 0; j < 8; ++j) {
        int c0 = part * 16 + j * 2;
        float e0 = tile[c0][kk], e1 = tile[c0 + 1][kk];
        er[j * 2] = e0; er[j * 2 + 1] = e1;
        s += e0 * e0 + e1 * e1;
        __half h0 = __float2half_rn(e0), h1 = __float2half_rn(e1);
        float l0 = e0 - __half2float(h0), l1 = e1 - __half2float(h1);
        sl += l0 * l0 + l1 * l1;
        hw[j] = (uint32_t)__half_as_ushort(h0) | ((uint32_t)__half_as_ushort(h1) << 16);
    }
    {
        uint4* dh = (uint4*)&g_eh[(k0 + kk) * C_DIM + part * 16];
        dh[0] = make_uint4(hw[0], hw[1], hw[2], hw[3]);
        dh[1] = make_uint4(hw[4], hw[5], hw[6], hw[7]);
        float4* dm = (float4*)&g_ecm[(k0 + kk) * C_DIM + part * 16];
#pragma unroll
        for (int q = 0; q < 4; ++q)
            dm[q] = make_float4(er[q*4], er[q*4+1], er[q*4+2], er[q*4+3]);
    }
    nred[part][kk] = s;
    nredl[part][kk] = sl;
    __syncthreads();
    if (part == 0) {
        float e2  = nred[0][kk] + nred[1][kk] + nred[2][kk] + nred[3][kk];
        float el2 = nredl[0][kk] + nredl[1][kk] + nredl[2][kk] + nredl[3][kk];
        g_enrm[k0 + kk] = e2;
        g_counts[k0 + kk] = 0;
        se2[kk] = e2;
        sel2[kk] = el2;
    }
    __syncthreads();
    if (tid < 32) {
        float m = fmaxf(se2[tid], se2[tid + 32]);
        float ml = fmaxf(sel2[tid], sel2[tid + 32]);
#pragma unroll
        for (int s2 = 16; s2 > 0; s2 >>= 1) {
            m  = fmaxf(m,  __shfl_xor_sync(0xFFFFFFFFu, m,  s2));
            ml = fmaxf(ml, __shfl_xor_sync(0xFFFFFFFFu, ml, s2));
        }
        if (tid == 0) { g_emax2[blockIdx.x] = m; g_elmax2[blockIdx.x] = ml; }
    }
    if (blockIdx.x == 0 && tid == 0) g_ticket = 0;
}

// ---------------------------------------------------------------------------
// Main: hh-only GEMM + branch-free packed-key top-2 argmin + exact refine.
// ---------------------------------------------------------------------------
__device__ __forceinline__ void load_chunk(int ck, int buf, uint32_t sb, int tid) {
    const __half* srch = g_eh + ck * CHUNK_K * C_DIM;
    const uint32_t dbase = sb + OFF_B + buf * PLANE_B;
#pragma unroll
    for (int p = 0; p < 4; ++p) {
        int i = tid + p * 256;                  // granule 0..1023
        int r = i >> 3, g = i & 7;
        cp16(dbase + (uint32_t)(r * PITCH_B + g * 16), srch + i * 8);
    }
    CP_COMMIT();
}

__global__ __launch_bounds__(256, 2) void vq_main(const float* __restrict__ inputs,
                                                  const float* __restrict__ embed,
                                                  float* __restrict__ out)
{
    extern __shared__ __align__(128) char smem[];
    const uint32_t sb = smem_u32(smem);
    const int tid = threadIdx.x;
    const int wid = tid >> 5, lane = tid & 31;
    const int mw = wid & 3, nh = wid >> 2;
    const int base_n = blockIdx.x * TILE_N;
    const int b = base_n >> 10, hw0 = base_n & 1023;

    float*    x32   = (float*)(smem + OFF_X32);
    float*    senrm = (float*)(smem + OFF_ENRM);   // enrm + 256
    uint32_t* cand  = (uint32_t*)(smem + OFF_CAND);
    int*      sidx  = (int*)(smem + OFF_SIDX);
    float*    sred  = (float*)(smem + OFF_SRED);

    load_chunk(0, 0, sb, tid);
    load_chunk(1, 1, sb, tid);

    for (int i = tid; i < K_CODES; i += 256) senrm[i] = g_enrm[i] + 256.0f;

    for (int idx = tid; idx < C_DIM * TILE_N; idx += 256) {
        int c = idx >> 7, nl = idx & 127;
        float x = inputs[b * 65536 + c * 1024 + hw0 + nl];
        x32[nl * XPITCH + c] = x;
        *(__half*)(smem + OFF_AH + nl * PITCH_B + c * 2) = __float2half_rn(x);
    }

    const uint32_t a_addr = sb + OFF_AH + (mw * 32 + (lane & 15)) * PITCH_B
                          + (lane >> 4) * 16;
    const int bm = lane >> 3, bsub = lane & 7;
    const uint32_t b_row_off = (uint32_t)(((bm >> 1) * 8 + bsub) * PITCH_B + (bm & 1) * 16);
    const int ntb = nh * 8;

    // packed top-2 trackers per (m, row-half) slot
    uint32_t p1[2][2] = {{0xFFFFFFFFu, 0xFFFFFFFFu}, {0xFFFFFFFFu, 0xFFFFFFFFu}};
    uint32_t p2[2][2] = {{0xFFFFFFFFu, 0xFFFFFFFFu}, {0xFFFFFFFFu, 0xFFFFFFFFu}};

    for (int ck = 0; ck < N_CHUNKS; ++ck) {
        const int buf = ck & 1;
        if (ck == N_CHUNKS - 1) { CP_WAIT(0); } else { CP_WAIT(1); }
        __syncthreads();

        float acc[2][8][4];
#pragma unroll
        for (int m = 0; m < 2; ++m)
#pragma unroll
            for (int t = 0; t < 8; ++t)
#pragma unroll
                for (int q = 0; q < 4; ++q) acc[m][t][q] = 0.f;

        const uint32_t bh_base = sb + OFF_B + buf * PLANE_B;
#pragma unroll
        for (int ks = 0; ks < 4; ++ks) {
            uint32_t ah[2][4];
#pragma unroll
            for (int m = 0; m < 2; ++m)
                LDSM_X4(ah[m][0], ah[m][1], ah[m][2], ah[m][3],
                        a_addr + m * 16 * PITCH_B + ks * 32);
#pragma unroll
            for (int p = 0; p < 4; ++p) {
                const int t0 = p * 2;
                uint32_t b0, b1, b2, b3;
                LDSM_X4(b0, b1, b2, b3,
                        bh_base + (uint32_t)((ntb + t0) * 8 * PITCH_B) + b_row_off + ks * 32);
                MMA16816(acc[0][t0][0],acc[0][t0][1],acc[0][t0][2],acc[0][t0][3],
                         ah[0][0],ah[0][1],ah[0][2],ah[0][3], b0,b1);
                MMA16816(acc[0][t0+1][0],acc[0][t0+1][1],acc[0][t0+1][2],acc[0][t0+1][3],
                         ah[0][0],ah[0][1],ah[0][2],ah[0][3], b2,b3);
                MMA16816(acc[1][t0][0],acc[1][t0][1],acc[1][t0][2],acc[1][t0][3],
                         ah[1][0],ah[1][1],ah[1][2],ah[1][3], b0,b1);
                MMA16816(acc[1][t0+1][0],acc[1][t0+1][1],acc[1][t0+1][2],acc[1][t0+1][3],
                         ah[1][0],ah[1][1],ah[1][2],ah[1][3], b2,b3);
            }
        }

        __syncthreads();
        if (ck + 2 < N_CHUNKS) load_chunk(ck + 2, buf, sb, tid);

        // branch-free packed-key top-2 epilogue
        const int k0c = ck * CHUNK_K;
#pragma unroll
        for (int t = 0; t < 8; ++t) {
            int kl = (ntb + t) * 8 + (lane & 3) * 2;
            float2 en = *(const float2*)(senrm + k0c + kl);
            uint32_t kc = (uint32_t)(k0c + kl);
#pragma unroll
            for (int m = 0; m < 2; ++m) {
                float d0 = fmaf(-2.f, acc[m][t][0], en.x);
                float d1 = fmaf(-2.f, acc[m][t][1], en.y);
                float d2 = fmaf(-2.f, acc[m][t][2], en.x);
                float d3 = fmaf(-2.f, acc[m][t][3], en.y);
                pk2_upd((__float_as_uint(d0) & 0xFFFFFC00u) | kc,        p1[m][0], p2[m][0]);
                pk2_upd((__float_as_uint(d1) & 0xFFFFFC00u) | (kc + 1u), p1[m][0], p2[m][0]);
                pk2_upd((__float_as_uint(d2) & 0xFFFFFC00u) | kc,        p1[m][1], p2[m][1]);
                pk2_upd((__float_as_uint(d3) & 0xFFFFFC00u) | (kc + 1u), p1[m][1], p2[m][1]);
            }
        }
    }

    // dump 16 packed lane-top2 candidates per vector
    {
        int rb = mw * 32 + (lane >> 2);
#pragma unroll
        for (int m = 0; m < 2; ++m)
#pragma unroll
            for (int h = 0; h < 2; ++h) {
                int v = rb + m * 16 + h * 8;
                cand[v * 16 + nh * 8 + (lane & 3) * 2]     = p1[m][h];
                cand[v * 16 + nh * 8 + (lane & 3) * 2 + 1] = p2[m][h];
            }
    }
    __syncthreads();

    // per-vector exact refine (thread v handles vector v)
    if (tid < TILE_N) {
        const int v = tid;
        float xh2 = 0.f, xl2 = 0.f;
#pragma unroll 8
        for (int c = 0; c < C_DIM; ++c) {
            float x = x32[v * XPITCH + c];
            float h = __half2float(__float2half_rn(x));
            float l = x - h;
            xh2 += h * h; xl2 += l * l;
        }
        float em2 = 0.f, elm2 = 0.f;
#pragma unroll
        for (int j = 0; j < PREP_BLKS; ++j) {
            em2 = fmaxf(em2, g_emax2[j]);
            elm2 = fmaxf(elm2, g_elmax2[j]);
        }
        // hh-error bound (x2 safety) + packing truncation slack + abs slack
        float eps = 4.2f * (sqrtf(xl2) * sqrtf(em2) + sqrtf(xh2) * sqrtf(elm2)) + 0.102f;

        uint32_t c16[16];
        uint32_t gp = 0xFFFFFFFFu;
#pragma unroll
        for (int j = 0; j < 16; ++j) {
            c16[j] = cand[v * 16 + j];
            gp = min(gp, c16[j]);
        }
        float thr = __uint_as_float(gp & 0xFFFFFC00u) + eps;   // +256 domain

        float bestd = 3.4e38f; int besti = K_CODES;
#pragma unroll
        for (int j = 0; j < 16; ++j) {
            float dj = __uint_as_float(c16[j] & 0xFFFFFC00u);
            if (dj <= thr) {
                int k = (int)(c16[j] & 1023u);
                const float4* er = (const float4*)(g_ecm + k * C_DIM);
                float dot = 0.f;
#pragma unroll
                for (int q = 0; q < 16; ++q) {
                    float4 e4 = __ldg(&er[q]);
                    dot += x32[v * XPITCH + q*4]     * e4.x
                         + x32[v * XPITCH + q*4 + 1] * e4.y
                         + x32[v * XPITCH + q*4 + 2] * e4.z
                         + x32[v * XPITCH + q*4 + 3] * e4.w;
                }
                float d = __ldg(&g_enrm[k]) - 2.f * dot;       // true domain
                if (d < bestd || (d == bestd && k < besti)) { bestd = d; besti = k; }
            }
        }
        sidx[v] = besti;
        out[IDX_OFF + base_n + v] = (float)besti;
        atomicAdd(&g_counts[besti], 1);
    }
    __syncthreads();

    // gather quantized, write coalesced, loss partial (deterministic order)
    float lsum = 0.f;
    for (int idx = tid; idx < C_DIM * TILE_N; idx += 256) {
        int c = idx >> 7, nl = idx & 127;
        int kq = sidx[nl];
        float q = __ldg(&embed[c * K_CODES + kq]);
        float x = x32[nl * XPITCH + c];
        out[b * 65536 + c * 1024 + hw0 + nl] = q;
        float dv = q - x;
        lsum += dv * dv;
    }
#pragma unroll
    for (int s = 16; s > 0; s >>= 1) lsum += __shfl_xor_sync(0xFFFFFFFFu, lsum, s);
    if (lane == 0) sred[wid] = lsum;
    __syncthreads();
    if (tid == 0) {
        float s = 0.f;
#pragma unroll
        for (int w = 0; w < 8; ++w) s += sred[w];
        g_loss_partial[blockIdx.x] = s;
    }

    // ---- last-CTA finalize (loss + perplexity), deterministic trees ----
    __threadfence();
    __syncthreads();
    int* flag = (int*)(smem + OFF_SRED + 32);
    if (tid == 0) {
        int old = atomicAdd(&g_ticket, 1);
        *flag = (old == N_BLOCKS - 1);
    }
    __syncthreads();
    if (*flag) {
        __threadfence();
        float* scr = (float*)(smem + OFF_SCR);
        float ps = 0.f;
#pragma unroll
        for (int j = 0; j < 4; ++j) {
            int k = tid + j * 256;
            float p = (float)g_counts[k] * (1.f / 32768.f);
            ps += p * logf(p + 1e-10f);
        }
        scr[tid] = ps;
        __syncthreads();
        for (int s = 128; s > 0; s >>= 1) {
            if (tid < s) scr[tid] += scr[tid + s];
            __syncthreads();
        }
        if (tid == 0) out[PERP_OFF] = expf(-scr[0]);
        __syncthreads();
        scr[tid] = g_loss_partial[tid];
        __syncthreads();
        for (int s = 128; s > 0; s >>= 1) {
            if (tid < s) scr[tid] += scr[tid + s];
            __syncthreads();
        }
        if (tid == 0) out[LOSS_OFF] = 0.25f * scr[0] / (float)Q_ELEMS;
    }
}

// ---------------------------------------------------------------------------
extern "C" void kernel_launch(void* const* d_in, const int* in_sizes, int n_in,
                              void* d_out, int out_size) {
    const float* inputs = (const float*)d_in[0];
    const float* embed  = (const float*)d_in[1];
    if (n_in >= 2 && in_sizes[0] == K_CODES * C_DIM && in_sizes[1] == Q_ELEMS) {
        const float* t = inputs; inputs = embed; embed = t;
    }
    float* out = (float*)d_out;

    static int smem_set = 0;
    if (!smem_set) {
        cudaFuncSetAttribute(vq_main, cudaFuncAttributeMaxDynamicSharedMemorySize,
                             SMEM_TOTAL);
        smem_set = 1;
    }

    vq_prep<<<PREP_BLKS, 256>>>(embed);
    vq_main<<<N_BLOCKS, 256, SMEM_TOTAL>>>(inputs, embed, out);
}

// round 17
// speedup vs baseline: 1.4326x; 1.0499x over previous
#include <cuda_runtime.h>
#include <cuda_fp16.h>
#include <math.h>
#include <stdint.h>

#define K_CODES 1024
#define C_DIM   64
#define N_TOT   32768
#define TILE_N  128
#define CHUNK_K 64
#define N_CHUNKS 16
#define N_BLOCKS (N_TOT / TILE_N)   // 256
#define PREP_BLKS 16

#define Q_ELEMS  (32*64*32*32)      // 2097152
#define LOSS_OFF Q_ELEMS
#define IDX_OFF  (Q_ELEMS + 1)
#define PERP_OFF (Q_ELEMS + 1 + N_TOT)

#define PITCH_B   144               // 9 x 16B: conflict-free ldmatrix rows
#define PLANE_BB  9216              // 64 rows x 144 B (one B chunk)
#define XPITCH    65

// smem layout (dynamic)
#define OFF_X32   0                 // 128 x 65 f32 = 33280
#define OFF_AH    33280             // 18432
#define OFF_B     51712             // 3 bufs x 9216 = 27648
#define OFF_ENRM  79360             // 1024 f32 (enrm + 256)
#define OFF_CAND  83456             // 128 x 16 u32 = 8192
#define OFF_SIDX  91648             // 128 ints
#define OFF_SRED  92160             // 8 f + flag
#define OFF_SCR   OFF_X32           // finalize scratch
#define SMEM_TOTAL 92224            // x2 = 184.4 KB/SM -> 2 CTAs/SM

// device scratch (no allocations allowed)
__device__ float  g_enrm[K_CODES];           // true ||e||^2
__device__ float  g_ecm[K_CODES * C_DIM];    // fp32 embed, code-major (refine)
__device__ int    g_counts[K_CODES];
__device__ float  g_loss_partial[N_BLOCKS];
__device__ int    g_ticket;
__device__ float  g_emax2[PREP_BLKS];
__device__ float  g_elmax2[PREP_BLKS];
__device__ __half g_eh[K_CODES * C_DIM];     // fp16 hi, code-major

__device__ __forceinline__ uint32_t smem_u32(const void* p) {
    uint32_t a;
    asm("{ .reg .u64 t; cvta.to.shared.u64 t, %1; cvt.u32.u64 %0, t; }" : "=r"(a) : "l"(p));
    return a;
}
__device__ __forceinline__ void cp16(uint32_t dst, const void* src) {
    asm volatile("cp.async.cg.shared.global [%0], [%1], 16;" :: "r"(dst), "l"(src));
}
#define CP_COMMIT() asm volatile("cp.async.commit_group;" ::: "memory")
#define CP_WAIT(n)  asm volatile("cp.async.wait_group %0;" :: "n"(n) : "memory")

#define LDSM_X4(r0,r1,r2,r3,a) \
    asm volatile("ldmatrix.sync.aligned.m8n8.x4.shared.b16 {%0,%1,%2,%3}, [%4];" \
                 : "=r"(r0),"=r"(r1),"=r"(r2),"=r"(r3) : "r"(a))
#define MMA16816(c0,c1,c2,c3,a0,a1,a2,a3,b0,b1) \
    asm volatile("mma.sync.aligned.m16n8k16.row.col.f32.f16.f16.f32 " \
                 "{%0,%1,%2,%3}, {%4,%5,%6,%7}, {%8,%9}, {%0,%1,%2,%3};" \
                 : "+f"(c0),"+f"(c1),"+f"(c2),"+f"(c3) \
                 : "r"(a0),"r"(a1),"r"(a2),"r"(a3),"r"(b0),"r"(b1))

// branch-free top-2 update on packed keys (3 IMNMX-class ops)
__device__ __forceinline__ void pk2_upd(uint32_t k, uint32_t& p1, uint32_t& p2) {
    uint32_t lo = min(p1, k);
    uint32_t hi = max(p1, k);
    p2 = min(p2, hi);
    p1 = lo;
}

// ---------------------------------------------------------------------------
// Prep: embed -> fp16 hi (code-major) + fp32 code-major copy, ||e||^2,
// split-norm maxima, zero counts, reset ticket.
// ---------------------------------------------------------------------------
__global__ __launch_bounds__(256) void vq_prep(const float* __restrict__ embed) {
    __shared__ float tile[64][65];
    __shared__ float nred[4][64], nredl[4][64];
    __shared__ float se2[64], sel2[64];
    const int tid = threadIdx.x;
    const int k0 = blockIdx.x * 64;

    for (int i = tid; i < 4096; i += 256) {
        int c = i >> 6, kk = i & 63;
        tile[c][kk] = embed[c * K_CODES + k0 + kk];
    }
    __syncthreads();

    const int kk = tid & 63, part = tid >> 6;
    float s = 0.f, sl = 0.f;
    uint32_t hw[8];
    float er[16];
#pragma unroll
    for (int j = 0; j < 8; ++j) {
        int c0 = part * 16 + j * 2;
        float e0 = tile[c0][kk], e1 = tile[c0 + 1][kk];
        er[j * 2] = e0; er[j * 2 + 1] = e1;
        s += e0 * e0 + e1 * e1;
        __half h0 = __float2half_rn(e0), h1 = __float2half_rn(e1);
        float l0 = e0 - __half2float(h0), l1 = e1 - __half2float(h1);
        sl += l0 * l0 + l1 * l1;
        hw[j] = (uint32_t)__half_as_ushort(h0) | ((uint32_t)__half_as_ushort(h1) << 16);
    }
    {
        uint4* dh = (uint4*)&g_eh[(k0 + kk) * C_DIM + part * 16];
        dh[0] = make_uint4(hw[0], hw[1], hw[2], hw[3]);
        dh[1] = make_uint4(hw[4], hw[5], hw[6], hw[7]);
        float4* dm = (float4*)&g_ecm[(k0 + kk) * C_DIM + part * 16];
#pragma unroll
        for (int q = 0; q < 4; ++q)
            dm[q] = make_float4(er[q*4], er[q*4+1], er[q*4+2], er[q*4+3]);
    }
    nred[part][kk] = s;
    nredl[part][kk] = sl;
    __syncthreads();
    if (part == 0) {
        float e2  = nred[0][kk] + nred[1][kk] + nred[2][kk] + nred[3][kk];
        float el2 = nredl[0][kk] + nredl[1][kk] + nredl[2][kk] + nredl[3][kk];
        g_enrm[k0 + kk] = e2;
        g_counts[k0 + kk] = 0;
        se2[kk] = e2;
        sel2[kk] = el2;
    }
    __syncthreads();
    if (tid < 32) {
        float m = fmaxf(se2[tid], se2[tid + 32]);
        float ml = fmaxf(sel2[tid], sel2[tid + 32]);
#pragma unroll
        for (int s2 = 16; s2 > 0; s2 >>= 1) {
            m  = fmaxf(m,  __shfl_xor_sync(0xFFFFFFFFu, m,  s2));
            ml = fmaxf(ml, __shfl_xor_sync(0xFFFFFFFFu, ml, s2));
        }
        if (tid == 0) { g_emax2[blockIdx.x] = m; g_elmax2[blockIdx.x] = ml; }
    }
    if (blockIdx.x == 0 && tid == 0) g_ticket = 0;
}

// ---------------------------------------------------------------------------
// Main: hh-only GEMM, 3-deep B buffers (1 barrier/chunk), branch-free packed
// top-2 epilogue of chunk k-1 pipelined into chunk k's MMA loop; exact refine.
// ---------------------------------------------------------------------------
__device__ __forceinline__ void load_chunk(int ck, int buf, uint32_t sb, int tid) {
    const __half* srch = g_eh + ck * CHUNK_K * C_DIM;
    const uint32_t dbase = sb + OFF_B + buf * PLANE_BB;
#pragma unroll
    for (int p = 0; p < 2; ++p) {
        int i = tid + p * 256;                  // granule 0..511
        int r = i >> 3, g = i & 7;
        cp16(dbase + (uint32_t)(r * PITCH_B + g * 16), srch + i * 8);
    }
    CP_COMMIT();
}

__device__ __forceinline__ void chunk_body(
    int ck, uint32_t sb, int tid, int lane, int nh,
    uint32_t a_addr, uint32_t b_row_off,
    float (&cur)[2][4][4], float (&prev)[2][4][4],
    uint32_t (&p1)[2][2], uint32_t (&p2)[2][2],
    const float* senrm)
{
    if (ck == N_CHUNKS - 1) { CP_WAIT(0); } else { CP_WAIT(1); }
    __syncthreads();    // chunk ck visible; all warps done reading buffer (ck+2)%3
    if (ck + 2 < N_CHUNKS) load_chunk(ck + 2, (ck + 2) % 3, sb, tid);

#pragma unroll
    for (int m = 0; m < 2; ++m)
#pragma unroll
        for (int t = 0; t < 4; ++t)
#pragma unroll
            for (int q = 0; q < 4; ++q) cur[m][t][q] = 0.f;

    const uint32_t bbase = sb + OFF_B + (uint32_t)((ck % 3) * PLANE_BB);
    const int pk0 = (ck - 1) * CHUNK_K;
#pragma unroll
    for (int ks = 0; ks < 4; ++ks) {
        uint32_t ah[2][4];
#pragma unroll
        for (int m = 0; m < 2; ++m)
            LDSM_X4(ah[m][0], ah[m][1], ah[m][2], ah[m][3],
                    a_addr + m * 16 * PITCH_B + ks * 32);
#pragma unroll
        for (int p = 0; p < 2; ++p) {
            const int t0 = p * 2;
            uint32_t b0, b1, b2, b3;
            LDSM_X4(b0, b1, b2, b3,
                    bbase + (uint32_t)((nh * 4 + t0) * 8 * PITCH_B) + b_row_off + ks * 32);
            MMA16816(cur[0][t0][0],cur[0][t0][1],cur[0][t0][2],cur[0][t0][3],
                     ah[0][0],ah[0][1],ah[0][2],ah[0][3], b0,b1);
            MMA16816(cur[0][t0+1][0],cur[0][t0+1][1],cur[0][t0+1][2],cur[0][t0+1][3],
                     ah[0][0],ah[0][1],ah[0][2],ah[0][3], b2,b3);
            MMA16816(cur[1][t0][0],cur[1][t0][1],cur[1][t0][2],cur[1][t0][3],
                     ah[1][0],ah[1][1],ah[1][2],ah[1][3], b0,b1);
            MMA16816(cur[1][t0+1][0],cur[1][t0+1][1],cur[1][t0+1][2],cur[1][t0+1][3],
                     ah[1][0],ah[1][1],ah[1][2],ah[1][3], b2,b3);
        }
        // pipelined branch-free epilogue: t=ks of PREVIOUS chunk
        if (ck > 0) {
            int kl = (nh * 4 + ks) * 8 + (lane & 3) * 2;
            float2 en = *(const float2*)(senrm + pk0 + kl);
            uint32_t kc = (uint32_t)(pk0 + kl);
#pragma unroll
            for (int m = 0; m < 2; ++m) {
                float d0 = fmaf(-2.f, prev[m][ks][0], en.x);
                float d1 = fmaf(-2.f, prev[m][ks][1], en.y);
                float d2 = fmaf(-2.f, prev[m][ks][2], en.x);
                float d3 = fmaf(-2.f, prev[m][ks][3], en.y);
                pk2_upd((__float_as_uint(d0) & 0xFFFFFC00u) | kc,        p1[m][0], p2[m][0]);
                pk2_upd((__float_as_uint(d1) & 0xFFFFFC00u) | (kc + 1u), p1[m][0], p2[m][0]);
                pk2_upd((__float_as_uint(d2) & 0xFFFFFC00u) | kc,        p1[m][1], p2[m][1]);
                pk2_upd((__float_as_uint(d3) & 0xFFFFFC00u) | (kc + 1u), p1[m][1], p2[m][1]);
            }
        }
    }
}

__global__ __launch_bounds__(256, 2) void vq_main(const float* __restrict__ inputs,
                                                  const float* __restrict__ embed,
                                                  float* __restrict__ out)
{
    extern __shared__ __align__(128) char smem[];
    const uint32_t sb = smem_u32(smem);
    const int tid = threadIdx.x;
    const int wid = tid >> 5, lane = tid & 31;
    const int mw = wid & 3, nh = wid >> 2;
    const int base_n = blockIdx.x * TILE_N;
    const int b = base_n >> 10, hw0 = base_n & 1023;

    float*    x32   = (float*)(smem + OFF_X32);
    float*    senrm = (float*)(smem + OFF_ENRM);   // enrm + 256
    uint32_t* cand  = (uint32_t*)(smem + OFF_CAND);
    int*      sidx  = (int*)(smem + OFF_SIDX);
    float*    sred  = (float*)(smem + OFF_SRED);

    load_chunk(0, 0, sb, tid);
    load_chunk(1, 1, sb, tid);

    for (int i = tid; i < K_CODES; i += 256) senrm[i] = g_enrm[i] + 256.0f;

    for (int idx = tid; idx < C_DIM * TILE_N; idx += 256) {
        int c = idx >> 7, nl = idx & 127;
        float x = inputs[b * 65536 + c * 1024 + hw0 + nl];
        x32[nl * XPITCH + c] = x;
        *(__half*)(smem + OFF_AH + nl * PITCH_B + c * 2) = __float2half_rn(x);
    }

    const uint32_t a_addr = sb + OFF_AH + (mw * 32 + (lane & 15)) * PITCH_B
                          + (lane >> 4) * 16;
    const int bm = lane >> 3, bsub = lane & 7;
    const uint32_t b_row_off = (uint32_t)(((bm >> 1) * 8 + bsub) * PITCH_B + (bm & 1) * 16);

    float accA[2][4][4], accB[2][4][4];
    uint32_t p1[2][2] = {{0xFFFFFFFFu, 0xFFFFFFFFu}, {0xFFFFFFFFu, 0xFFFFFFFFu}};
    uint32_t p2[2][2] = {{0xFFFFFFFFu, 0xFFFFFFFFu}, {0xFFFFFFFFu, 0xFFFFFFFFu}};

    for (int ck2 = 0; ck2 < N_CHUNKS; ck2 += 2) {
        chunk_body(ck2,     sb, tid, lane, nh, a_addr, b_row_off,
                   accA, accB, p1, p2, senrm);
        chunk_body(ck2 + 1, sb, tid, lane, nh, a_addr, b_row_off,
                   accB, accA, p1, p2, senrm);
    }
    // final epilogue: chunk 15 results live in accB
    {
        const int pk0 = (N_CHUNKS - 1) * CHUNK_K;
#pragma unroll
        for (int t = 0; t < 4; ++t) {
            int kl = (nh * 4 + t) * 8 + (lane & 3) * 2;
            float2 en = *(const float2*)(senrm + pk0 + kl);
            uint32_t kc = (uint32_t)(pk0 + kl);
#pragma unroll
            for (int m = 0; m < 2; ++m) {
                float d0 = fmaf(-2.f, accB[m][t][0], en.x);
                float d1 = fmaf(-2.f, accB[m][t][1], en.y);
                float d2 = fmaf(-2.f, accB[m][t][2], en.x);
                float d3 = fmaf(-2.f, accB[m][t][3], en.y);
                pk2_upd((__float_as_uint(d0) & 0xFFFFFC00u) | kc,        p1[m][0], p2[m][0]);
                pk2_upd((__float_as_uint(d1) & 0xFFFFFC00u) | (kc + 1u), p1[m][0], p2[m][0]);
                pk2_upd((__float_as_uint(d2) & 0xFFFFFC00u) | kc,        p1[m][1], p2[m][1]);
                pk2_upd((__float_as_uint(d3) & 0xFFFFFC00u) | (kc + 1u), p1[m][1], p2[m][1]);
            }
        }
    }

    // dump 16 packed lane-top2 candidates per vector
    {
        int rb = mw * 32 + (lane >> 2);
#pragma unroll
        for (int m = 0; m < 2; ++m)
#pragma unroll
            for (int h = 0; h < 2; ++h) {
                int v = rb + m * 16 + h * 8;
                cand[v * 16 + nh * 8 + (lane & 3) * 2]     = p1[m][h];
                cand[v * 16 + nh * 8 + (lane & 3) * 2 + 1] = p2[m][h];
            }
    }
    __syncthreads();

    // per-vector exact refine (thread v handles vector v)
    if (tid < TILE_N) {
        const int v = tid;
        float xh2 = 0.f, xl2 = 0.f;
#pragma unroll 8
        for (int c = 0; c < C_DIM; ++c) {
            float x = x32[v * XPITCH + c];
            float h = __half2float(__float2half_rn(x));
            float l = x - h;
            xh2 += h * h; xl2 += l * l;
        }
        float em2 = 0.f, elm2 = 0.f;
#pragma unroll
        for (int j = 0; j < PREP_BLKS; ++j) {
            em2 = fmaxf(em2, g_emax2[j]);
            elm2 = fmaxf(elm2, g_elmax2[j]);
        }
        // hh-error bound (x2 safety) + packing truncation slack + abs slack
        float eps = 4.2f * (sqrtf(xl2) * sqrtf(em2) + sqrtf(xh2) * sqrtf(elm2)) + 0.102f;

        uint32_t c16[16];
        uint32_t gp = 0xFFFFFFFFu;
#pragma unroll
        for (int j = 0; j < 16; ++j) {
            c16[j] = cand[v * 16 + j];
            gp = min(gp, c16[j]);
        }
        float thr = __uint_as_float(gp & 0xFFFFFC00u) + eps;   // +256 domain

        float bestd = 3.4e38f; int besti = K_CODES;
#pragma unroll
        for (int j = 0; j < 16; ++j) {
            float dj = __uint_as_float(c16[j] & 0xFFFFFC00u);
            if (dj <= thr) {
                int k = (int)(c16[j] & 1023u);
                const float4* er = (const float4*)(g_ecm + k * C_DIM);
                float dot = 0.f;
#pragma unroll
                for (int q = 0; q < 16; ++q) {
                    float4 e4 = __ldg(&er[q]);
                    dot += x32[v * XPITCH + q*4]     * e4.x
                         + x32[v * XPITCH + q*4 + 1] * e4.y
                         + x32[v * XPITCH + q*4 + 2] * e4.z
                         + x32[v * XPITCH + q*4 + 3] * e4.w;
                }
                float d = __ldg(&g_enrm[k]) - 2.f * dot;       // true domain
                if (d < bestd || (d == bestd && k < besti)) { bestd = d; besti = k; }
            }
        }
        sidx[v] = besti;
        out[IDX_OFF + base_n + v] = (float)besti;
        atomicAdd(&g_counts[besti], 1);
    }
    __syncthreads();

    // gather quantized, write coalesced, loss partial (deterministic order)
    float lsum = 0.f;
    for (int idx = tid; idx < C_DIM * TILE_N; idx += 256) {
        int c = idx >> 7, nl = idx & 127;
        int kq = sidx[nl];
        float q = __ldg(&embed[c * K_CODES + kq]);
        float x = x32[nl * XPITCH + c];
        out[b * 65536 + c * 1024 + hw0 + nl] = q;
        float dv = q - x;
        lsum += dv * dv;
    }
#pragma unroll
    for (int s = 16; s > 0; s >>= 1) lsum += __shfl_xor_sync(0xFFFFFFFFu, lsum, s);
    if (lane == 0) sred[wid] = lsum;
    __syncthreads();
    if (tid == 0) {
        float s = 0.f;
#pragma unroll
        for (int w = 0; w < 8; ++w) s += sred[w];
        g_loss_partial[blockIdx.x] = s;
    }

    // ---- last-CTA finalize (loss + perplexity), deterministic trees ----
    __threadfence();
    __syncthreads();
    int* flag = (int*)(smem + OFF_SRED + 32);
    if (tid == 0) {
        int old = atomicAdd(&g_ticket, 1);
        *flag = (old == N_BLOCKS - 1);
    }
    __syncthreads();
    if (*flag) {
        __threadfence();
        float* scr = (float*)(smem + OFF_SCR);
        float ps = 0.f;
#pragma unroll
        for (int j = 0; j < 4; ++j) {
            int k = tid + j * 256;
            float p = (float)g_counts[k] * (1.f / 32768.f);
            ps += p * logf(p + 1e-10f);
        }
        scr[tid] = ps;
        __syncthreads();
        for (int s = 128; s > 0; s >>= 1) {
            if (tid < s) scr[tid] += scr[tid + s];
            __syncthreads();
        }
        if (tid == 0) out[PERP_OFF] = expf(-scr[0]);
        __syncthreads();
        scr[tid] = g_loss_partial[tid];
        __syncthreads();
        for (int s = 128; s > 0; s >>= 1) {
            if (tid < s) scr[tid] += scr[tid + s];
            __syncthreads();
        }
        if (tid == 0) out[LOSS_OFF] = 0.25f * scr[0] / (float)Q_ELEMS;
    }
}

// ---------------------------------------------------------------------------
extern "C" void kernel_launch(void* const* d_in, const int* in_sizes, int n_in,
                              void* d_out, int out_size) {
    const float* inputs = (const float*)d_in[0];
    const float* embed  = (const float*)d_in[1];
    if (n_in >= 2 && in_sizes[0] == K_CODES * C_DIM && in_sizes[1] == Q_ELEMS) {
        const float* t = inputs; inputs = embed; embed = t;
    }
    float* out = (float*)d_out;

    static int smem_set = 0;
    if (!smem_set) {
        cudaFuncSetAttribute(vq_main, cudaFuncAttributeMaxDynamicSharedMemorySize,
                             SMEM_TOTAL);
        smem_set = 1;
    }

    vq_prep<<<PREP_BLKS, 256>>>(embed);
    vq_main<<<N_BLOCKS, 256, SMEM_TOTAL>>>(inputs, embed, out);
}